// round 2
// baseline (speedup 1.0000x reference)
#include <cuda_runtime.h>

// Problem constants (fixed shapes for this problem)
#define N_TOK 4096          // B*S = 2*2048
#define DIM   1024
#define NE    8             // experts
#define CAP   1280          // floor(2*1.25*4096/8), already even
#define NEC   ((size_t)N_TOK * NE * CAP)   // 41,943,040
#define ECD   ((size_t)NE * CAP * DIM)     // 10,485,760

// Scratch (no allocations allowed -> device globals)
__device__ int   g_top[2][N_TOK];
__device__ float g_prob[2][N_TOK];
__device__ int   g_slot_token[NE * CAP];

// ---------------------------------------------------------------------------
// Kernel 1: router logits + top-2 + 2-way softmax. One warp per token.
// ---------------------------------------------------------------------------
__global__ void k_logits(const float* __restrict__ x,
                         const float* __restrict__ w,
                         float* __restrict__ logits_out) {
    __shared__ float ws[NE * DIM];   // 32 KB
    int tid = threadIdx.x;
    for (int i = tid; i < NE * DIM; i += blockDim.x) ws[i] = w[i];
    __syncthreads();

    int warp = tid >> 5, lane = tid & 31;
    int n = blockIdx.x * 8 + warp;
    if (n >= N_TOK) return;

    const float* xr = x + (size_t)n * DIM;
    float acc[NE];
#pragma unroll
    for (int e = 0; e < NE; e++) acc[e] = 0.f;

    for (int i = lane; i < DIM; i += 32) {
        float xv = xr[i];
#pragma unroll
        for (int e = 0; e < NE; e++) acc[e] = fmaf(xv, ws[e * DIM + i], acc[e]);
    }
#pragma unroll
    for (int e = 0; e < NE; e++) {
#pragma unroll
        for (int o = 16; o > 0; o >>= 1)
            acc[e] += __shfl_down_sync(0xffffffffu, acc[e], o);
    }

    if (lane == 0) {
        // top-2 with jax.lax.top_k tie-breaking (first/lowest index wins)
        int i0 = 0; float v0 = acc[0];
#pragma unroll
        for (int e = 1; e < NE; e++) { if (acc[e] > v0) { v0 = acc[e]; i0 = e; } }
        int i1 = -1; float v1 = -INFINITY;
#pragma unroll
        for (int e = 0; e < NE; e++) {
            if (e != i0 && acc[e] > v1) { v1 = acc[e]; i1 = e; }
        }
        float t  = expf(v1 - v0);          // <= 1
        float den = 1.f + t;
        g_top[0][n]  = i0;
        g_top[1][n]  = i1;
        g_prob[0][n] = 1.f / den;
        g_prob[1][n] = t / den;
#pragma unroll
        for (int e = 0; e < NE; e++) logits_out[(size_t)n * NE + e] = acc[e];
    }
}

// ---------------------------------------------------------------------------
// Kernel 2: ordered per-expert rank scan over the 2*N assignments in k-major
// order (all k=0 assignments in token order, then all k=1). Single block,
// 1024 threads x 8 items. Scatters nonzero weight/mask entries and fills the
// slot->token map for the batch-gather kernel.
// ---------------------------------------------------------------------------
__global__ void k_scan(float* __restrict__ out_w, float* __restrict__ out_m) {
    const int IPT = (2 * N_TOK) / 1024;   // 8 items per thread
    int tid  = threadIdx.x;
    int lane = tid & 31, warp = tid >> 5;

    // init slot map
    for (int i = tid; i < NE * CAP; i += 1024) g_slot_token[i] = -1;
    __syncthreads();

    // local per-expert counts
    int cnt[NE];
#pragma unroll
    for (int e = 0; e < NE; e++) cnt[e] = 0;
    int ex[IPT];
    int j0 = tid * IPT;
#pragma unroll
    for (int i = 0; i < IPT; i++) {
        int j = j0 + i;
        int k = (j >= N_TOK) ? 1 : 0;
        int n = j - k * N_TOK;
        int e = g_top[k][n];
        ex[i] = e;
        cnt[e]++;
    }

    // inclusive warp scan per expert
    int incl[NE];
#pragma unroll
    for (int e = 0; e < NE; e++) {
        int v = cnt[e];
#pragma unroll
        for (int o = 1; o < 32; o <<= 1) {
            int u = __shfl_up_sync(0xffffffffu, v, o);
            if (lane >= o) v += u;
        }
        incl[e] = v;
    }

    __shared__ int wtot[32][NE];
    __shared__ int wbase[32][NE];
    if (lane == 31) {
#pragma unroll
        for (int e = 0; e < NE; e++) wtot[warp][e] = incl[e];
    }
    __syncthreads();
    if (warp == 0) {
#pragma unroll
        for (int e = 0; e < NE; e++) {
            int v = wtot[lane][e];
            int iv = v;
#pragma unroll
            for (int o = 1; o < 32; o <<= 1) {
                int u = __shfl_up_sync(0xffffffffu, iv, o);
                if (lane >= o) iv += u;
            }
            wbase[lane][e] = iv - v;   // exclusive across warps
        }
    }
    __syncthreads();

    int base[NE];
#pragma unroll
    for (int e = 0; e < NE; e++) base[e] = wbase[warp][e] + incl[e] - cnt[e];

    // replay in order, assign ranks, scatter
#pragma unroll
    for (int i = 0; i < IPT; i++) {
        int j = j0 + i;
        int k = (j >= N_TOK) ? 1 : 0;
        int n = j - k * N_TOK;
        int e = ex[i];
        int r = base[e]++;
        if (r < CAP) {
            float p = g_prob[k][n];
            if (p > 0.f) {
                size_t idx = (size_t)n * (NE * CAP) + (size_t)e * CAP + r;
                out_w[idx] = p;
                out_m[idx] = 1.0f;
                g_slot_token[e * CAP + r] = n;
            }
        }
    }
}

// ---------------------------------------------------------------------------
// Kernel 3: expert batches. One block per (expert, slot): copy token row or
// write zeros. 256 threads x float4 == 1024 floats.
// ---------------------------------------------------------------------------
__global__ void k_batches(const float* __restrict__ x, float* __restrict__ out_b) {
    int slot = blockIdx.x;
    int n = g_slot_token[slot];
    float4* dst = (float4*)(out_b + (size_t)slot * DIM);
    int t = threadIdx.x;
    if (n >= 0) {
        const float4* src = (const float4*)(x + (size_t)n * DIM);
        dst[t] = src[t];
    } else {
        dst[t] = make_float4(0.f, 0.f, 0.f, 0.f);
    }
}

// ---------------------------------------------------------------------------
extern "C" void kernel_launch(void* const* d_in, const int* in_sizes, int n_in,
                              void* d_out, int out_size) {
    const float* x = (const float*)d_in[0];
    const float* w = (const float*)d_in[1];
    // defensive: identify inputs by size (x = 4,194,304; w_gate = 8,192)
    if (in_sizes[0] == NE * DIM && in_sizes[1] == N_TOK * DIM) {
        const float* tmp = x; x = w; w = tmp;
    }

    float* out   = (float*)d_out;
    float* out_w = out;                    // [N, E, cap]
    float* out_m = out + NEC;              // [N, E, cap] (bool as float)
    float* out_b = out + 2 * NEC;          // [E, cap, D]
    float* out_l = out + 2 * NEC + ECD;    // [B, S, E]

    // zero the sparse weight/mask regions (335 MB: the dominant cost)
    cudaMemsetAsync(out, 0, 2 * NEC * sizeof(float), 0);

    k_logits<<<N_TOK / 8, 256>>>(x, w, out_l);
    k_scan<<<1, 1024>>>(out_w, out_m);
    k_batches<<<NE * CAP, 256>>>(x, out_b);
}

// round 3
// speedup vs baseline: 1.0714x; 1.0714x over previous
#include <cuda_runtime.h>

// Problem constants (fixed shapes)
#define N_TOK 4096          // B*S = 2*2048
#define DIM   1024
#define NE    8             // experts
#define CAP   1280
#define NEC   ((size_t)N_TOK * NE * CAP)   // 41,943,040 floats
#define ECD   ((size_t)NE * CAP * DIM)     // 10,485,760 floats

#define LOGITS_BLOCKS (N_TOK / 8)          // 512 (8 tokens/block, warp per token)
#define ZERO_BLOCKS   4096
#define ZERO_F4       (2 * NEC / 4)        // 20,971,520 float4 (w + m regions)
// ZERO_F4 / (ZERO_BLOCKS*256) = 20 exactly

// Scratch (no allocations allowed -> device globals)
__device__ int   g_top[2][N_TOK];
__device__ float g_prob[2][N_TOK];
__device__ int   g_slot_token[NE * CAP];

// ---------------------------------------------------------------------------
// Kernel 1 (fused): block-specialized.
//   blocks [0, 512):    router logits + top-2 + 2-way softmax (warp/token)
//   blocks [512, 4608): zero-fill the weight+mask output regions (335 MB)
// The zero traffic saturates DRAM writes while logits compute rides along.
// ---------------------------------------------------------------------------
__global__ void k_main(const float* __restrict__ x,
                       const float* __restrict__ w,
                       float* __restrict__ out_zero_base,   // = out_w (w+m contiguous)
                       float* __restrict__ logits_out) {
    if (blockIdx.x >= LOGITS_BLOCKS) {
        // ---- zero path: 128-bit stores, fully coalesced, no smem use ----
        float4* dst = (float4*)out_zero_base;
        unsigned t0 = (blockIdx.x - LOGITS_BLOCKS) * blockDim.x + threadIdx.x;
        const unsigned stride = ZERO_BLOCKS * 256;
        float4 z = make_float4(0.f, 0.f, 0.f, 0.f);
#pragma unroll
        for (int k = 0; k < 20; k++)
            dst[t0 + (size_t)k * stride] = z;
        return;
    }

    // ---- logits path ----
    __shared__ float4 ws4[NE * (DIM / 4)];   // 32 KB
    int tid = threadIdx.x;
    const float4* w4 = (const float4*)w;
    for (int i = tid; i < NE * (DIM / 4); i += blockDim.x) ws4[i] = w4[i];
    __syncthreads();

    int warp = tid >> 5, lane = tid & 31;
    int n = blockIdx.x * 8 + warp;

    const float4* xr = (const float4*)(x + (size_t)n * DIM);
    float acc[NE];
#pragma unroll
    for (int e = 0; e < NE; e++) acc[e] = 0.f;

#pragma unroll
    for (int ii = 0; ii < (DIM / 4) / 32; ii++) {       // 8 iterations
        int i = lane + ii * 32;
        float4 xv = xr[i];
#pragma unroll
        for (int e = 0; e < NE; e++) {
            float4 wv = ws4[e * (DIM / 4) + i];
            acc[e] = fmaf(xv.x, wv.x, acc[e]);
            acc[e] = fmaf(xv.y, wv.y, acc[e]);
            acc[e] = fmaf(xv.z, wv.z, acc[e]);
            acc[e] = fmaf(xv.w, wv.w, acc[e]);
        }
    }
#pragma unroll
    for (int e = 0; e < NE; e++) {
#pragma unroll
        for (int o = 16; o > 0; o >>= 1)
            acc[e] += __shfl_down_sync(0xffffffffu, acc[e], o);
    }

    if (lane == 0) {
        // top-2 with jax.lax.top_k tie-breaking (lowest index wins)
        int i0 = 0; float v0 = acc[0];
#pragma unroll
        for (int e = 1; e < NE; e++) { if (acc[e] > v0) { v0 = acc[e]; i0 = e; } }
        int i1 = -1; float v1 = -INFINITY;
#pragma unroll
        for (int e = 0; e < NE; e++) {
            if (e != i0 && acc[e] > v1) { v1 = acc[e]; i1 = e; }
        }
        float t   = expf(v1 - v0);          // <= 1
        float den = 1.f + t;
        g_top[0][n]  = i0;
        g_top[1][n]  = i1;
        g_prob[0][n] = 1.f / den;
        g_prob[1][n] = t / den;
#pragma unroll
        for (int e = 0; e < NE; e++) logits_out[(size_t)n * NE + e] = acc[e];
    }
}

// ---------------------------------------------------------------------------
// Kernel 2: ordered per-expert rank scan over the 2*N assignments in k-major
// order. Single block, 1024 threads x 8 items. Scatters the nonzero entries
// into the (already zeroed) weight/mask regions and fills the slot->token map.
// ---------------------------------------------------------------------------
__global__ void k_scan(float* __restrict__ out_w, float* __restrict__ out_m) {
    const int IPT = (2 * N_TOK) / 1024;   // 8
    int tid  = threadIdx.x;
    int lane = tid & 31, warp = tid >> 5;

    for (int i = tid; i < NE * CAP; i += 1024) g_slot_token[i] = -1;
    __syncthreads();

    int cnt[NE];
#pragma unroll
    for (int e = 0; e < NE; e++) cnt[e] = 0;
    int ex[IPT];
    int j0 = tid * IPT;
#pragma unroll
    for (int i = 0; i < IPT; i++) {
        int j = j0 + i;
        int k = (j >= N_TOK) ? 1 : 0;
        int n = j - k * N_TOK;
        int e = g_top[k][n];
        ex[i] = e;
        cnt[e]++;
    }

    int incl[NE];
#pragma unroll
    for (int e = 0; e < NE; e++) {
        int v = cnt[e];
#pragma unroll
        for (int o = 1; o < 32; o <<= 1) {
            int u = __shfl_up_sync(0xffffffffu, v, o);
            if (lane >= o) v += u;
        }
        incl[e] = v;
    }

    __shared__ int wtot[32][NE];
    __shared__ int wbase[32][NE];
    if (lane == 31) {
#pragma unroll
        for (int e = 0; e < NE; e++) wtot[warp][e] = incl[e];
    }
    __syncthreads();
    if (warp == 0) {
#pragma unroll
        for (int e = 0; e < NE; e++) {
            int v = wtot[lane][e];
            int iv = v;
#pragma unroll
            for (int o = 1; o < 32; o <<= 1) {
                int u = __shfl_up_sync(0xffffffffu, iv, o);
                if (lane >= o) iv += u;
            }
            wbase[lane][e] = iv - v;
        }
    }
    __syncthreads();

    int base[NE];
#pragma unroll
    for (int e = 0; e < NE; e++) base[e] = wbase[warp][e] + incl[e] - cnt[e];

#pragma unroll
    for (int i = 0; i < IPT; i++) {
        int j = j0 + i;
        int k = (j >= N_TOK) ? 1 : 0;
        int n = j - k * N_TOK;
        int e = ex[i];
        int r = base[e]++;
        if (r < CAP) {
            float p = g_prob[k][n];
            if (p > 0.f) {
                size_t idx = (size_t)n * (NE * CAP) + (size_t)e * CAP + r;
                out_w[idx] = p;
                out_m[idx] = 1.0f;
                g_slot_token[e * CAP + r] = n;
            }
        }
    }
}

// ---------------------------------------------------------------------------
// Kernel 3: expert batches. One block per (expert, slot): copy token row or
// write zeros. 256 threads x float4 == 1024 floats.
// ---------------------------------------------------------------------------
__global__ void k_batches(const float* __restrict__ x, float* __restrict__ out_b) {
    int slot = blockIdx.x;
    int n = g_slot_token[slot];
    float4* dst = (float4*)(out_b + (size_t)slot * DIM);
    int t = threadIdx.x;
    if (n >= 0) {
        const float4* src = (const float4*)(x + (size_t)n * DIM);
        dst[t] = src[t];
    } else {
        dst[t] = make_float4(0.f, 0.f, 0.f, 0.f);
    }
}

// ---------------------------------------------------------------------------
extern "C" void kernel_launch(void* const* d_in, const int* in_sizes, int n_in,
                              void* d_out, int out_size) {
    const float* x = (const float*)d_in[0];
    const float* w = (const float*)d_in[1];
    if (in_sizes[0] == NE * DIM && in_sizes[1] == N_TOK * DIM) {
        const float* tmp = x; x = w; w = tmp;
    }

    float* out   = (float*)d_out;
    float* out_w = out;                    // [N, E, cap]
    float* out_m = out + NEC;              // [N, E, cap] (bool as float)
    float* out_b = out + 2 * NEC;          // [E, cap, D]
    float* out_l = out + 2 * NEC + ECD;    // [B, S, E]

    k_main<<<LOGITS_BLOCKS + ZERO_BLOCKS, 256>>>(x, w, out_w, out_l);
    k_scan<<<1, 1024>>>(out_w, out_m);
    k_batches<<<NE * CAP, 256>>>(x, out_b);
}